// round 1
// baseline (speedup 1.0000x reference)
#include <cuda_runtime.h>

// ---------------------------------------------------------------------------
// EnergySRB: srb = pre[s0,s1] * exp(dfac[s0,s1]*d) * smooth_cutoff(d, rc)
//            out[mol] = energies[mol] + segment_sum(srb, mol = i0 / n_atoms)
// ---------------------------------------------------------------------------

#define A2B_F 1.8897261258369282f
#define RC_F 9.826575854352027f          // 5.2 * A2B
#define INV_RC_F (1.0f / RC_F)

#define MAX_ATOKENS (512 * 1024)          // max total atoms for packed path
#define MAX_MOLS (8192)
#define BIN_STRIDE 132                    // 528B stride -> spreads L2 slice hash

__device__ unsigned int g_packed[MAX_ATOKENS / 16];   // 2-bit species codes
__device__ float g_bins[MAX_MOLS * BIN_STRIDE];       // padded molecule bins

// ---------------------------------------------------------------------------
// Init: pack species to 2 bits, zero the (strided) bins
// ---------------------------------------------------------------------------
__global__ void init_kernel(const int* __restrict__ species, int n_sp,
                            int n_mol, int bin_stride, int do_pack) {
    int t = blockIdx.x * blockDim.x + threadIdx.x;
    if (do_pack) {
        int nwords = (n_sp + 15) >> 4;
        if (t < nwords) {
            unsigned int w = 0;
            int base = t << 4;
            #pragma unroll
            for (int j = 0; j < 16; j++) {
                int a = base + j;
                unsigned int v = (a < n_sp) ? ((unsigned int)species[a] & 3u) : 0u;
                w |= v << (2 * j);
            }
            g_packed[t] = w;
        }
    }
    if (t < n_mol) g_bins[t * bin_stride] = 0.0f;
}

// ---------------------------------------------------------------------------
// Main pair kernel
// ---------------------------------------------------------------------------
__device__ __forceinline__ void process_pair(
    int i0, int i1, float dist_ang,
    const float2* __restrict__ s_tab, int n_elem,
    int na_shift, int n_atoms, int bin_stride,
    const int* __restrict__ species, bool packed)
{
    int s0, s1;
    if (packed) {
        unsigned int w0 = g_packed[i0 >> 4];
        unsigned int w1 = g_packed[i1 >> 4];
        s0 = (int)((w0 >> ((i0 & 15) << 1)) & 3u);
        s1 = (int)((w1 >> ((i1 & 15) << 1)) & 3u);
    } else {
        s0 = species[i0];
        s1 = species[i1];
    }
    float2 c = s_tab[s0 * n_elem + s1];   // (pre, dfac)
    float d = dist_ang * A2B_F;
    float x = d * INV_RC_F;
    float u = fmaf(-x, x, 1.0f);          // 1 - (d/rc)^2
    int mol = (na_shift >= 0) ? (i0 >> na_shift) : (i0 / n_atoms);
    if (u > 0.0f) {
        // fuse both exps: exp(dfac*d) * exp(1 - 1/u) = exp(dfac*d + 1 - 1/u)
        float e = fmaf(c.y, d, 1.0f - __frcp_rn(u));
        float srb = c.x * __expf(e);
        atomicAdd(&g_bins[mol * bin_stride], srb);   // RED.F32 (result unused)
    }
}

template <bool PACKED>
__global__ void __launch_bounds__(256)
srb_kernel(const int* __restrict__ idx0, const int* __restrict__ idx1,
           const float* __restrict__ dist, const int* __restrict__ species,
           const float* __restrict__ pre_tab, const float* __restrict__ dfac_tab,
           int P, int n_elem, int na_shift, int n_atoms, int bin_stride)
{
    __shared__ float2 s_tab[64];
    int ne2 = n_elem * n_elem;
    for (int j = threadIdx.x; j < ne2; j += blockDim.x)
        s_tab[j] = make_float2(pre_tab[j], dfac_tab[j]);
    __syncthreads();

    int tid = blockIdx.x * blockDim.x + threadIdx.x;
    int stride = gridDim.x * blockDim.x;
    int nv = P >> 2;

    const int4* __restrict__ v0 = (const int4*)idx0;
    const int4* __restrict__ v1 = (const int4*)idx1;
    const float4* __restrict__ vd = (const float4*)dist;

    for (int i = tid; i < nv; i += stride) {
        // streaming loads: evict-first so the hot packed-species table stays in L1
        int4 a = __ldcs(v0 + i);
        int4 b = __ldcs(v1 + i);
        float4 dd = __ldcs(vd + i);
        process_pair(a.x, b.x, dd.x, s_tab, n_elem, na_shift, n_atoms, bin_stride, species, PACKED);
        process_pair(a.y, b.y, dd.y, s_tab, n_elem, na_shift, n_atoms, bin_stride, species, PACKED);
        process_pair(a.z, b.z, dd.z, s_tab, n_elem, na_shift, n_atoms, bin_stride, species, PACKED);
        process_pair(a.w, b.w, dd.w, s_tab, n_elem, na_shift, n_atoms, bin_stride, species, PACKED);
    }

    // tail (P % 4)
    int rem = P & 3;
    if (tid < rem) {
        int p = (nv << 2) + tid;
        process_pair(idx0[p], idx1[p], dist[p], s_tab, n_elem, na_shift, n_atoms,
                     bin_stride, species, PACKED);
    }
}

// ---------------------------------------------------------------------------
// Finalize: out = [species (as float), energies + bins]  or just the energies
// ---------------------------------------------------------------------------
__global__ void finalize_kernel(const float* __restrict__ energies,
                                const int* __restrict__ species,
                                float* __restrict__ out,
                                int n_mol, int n_sp, int bin_stride, int mode) {
    int t = blockIdx.x * blockDim.x + threadIdx.x;
    if (mode == 1) {
        if (t < n_sp) out[t] = (float)species[t];
        if (t < n_mol) out[n_sp + t] = energies[t] + g_bins[t * bin_stride];
    } else if (mode == 2) {
        // species-only output (unlikely, defensive)
        if (t < n_sp) out[t] = (float)species[t];
    } else {
        if (t < n_mol) out[t] = energies[t] + g_bins[t * bin_stride];
    }
}

// ---------------------------------------------------------------------------
extern "C" void kernel_launch(void* const* d_in, const int* in_sizes, int n_in,
                              void* d_out, int out_size) {
    const int*   species  = (const int*)d_in[0];
    const float* energies = (const float*)d_in[1];
    const int*   ai12     = (const int*)d_in[2];
    const float* dist     = (const float*)d_in[3];
    const float* pre_tab  = (const float*)d_in[4];
    const float* dfac_tab = (const float*)d_in[5];

    int n_sp  = in_sizes[0];
    int n_mol = in_sizes[1];
    int P     = in_sizes[3];
    int n_atoms = (n_mol > 0) ? (n_sp / n_mol) : 1;
    if (n_atoms < 1) n_atoms = 1;

    int n_elem = 1;
    while (n_elem * n_elem < in_sizes[4]) n_elem++;

    int na_shift = -1;
    if ((n_atoms & (n_atoms - 1)) == 0) {
        int s = 0; int v = n_atoms;
        while (v > 1) { v >>= 1; s++; }
        na_shift = s;
    }

    bool packed = (n_elem <= 4) && (n_sp <= MAX_ATOKENS);
    int bin_stride = (n_mol <= MAX_MOLS) ? BIN_STRIDE : 1;  // fallback: dense bins

    // init: pack + zero bins
    int init_n = n_mol;
    int nwords = (n_sp + 15) >> 4;
    if (packed && nwords > init_n) init_n = nwords;
    int init_grid = (init_n + 255) / 256;
    init_kernel<<<init_grid, 256>>>(species, n_sp, n_mol, bin_stride, packed ? 1 : 0);

    // main
    const int* idx0 = ai12;
    const int* idx1 = ai12 + P;
    int nv = P >> 2;
    long long want = ((long long)nv + 255) / 256;
    int grid = (want > 1184) ? 1184 : (int)want;
    if (grid < 1) grid = 1;
    if (packed)
        srb_kernel<true><<<grid, 256>>>(idx0, idx1, dist, species, pre_tab, dfac_tab,
                                        P, n_elem, na_shift, n_atoms, bin_stride);
    else
        srb_kernel<false><<<grid, 256>>>(idx0, idx1, dist, species, pre_tab, dfac_tab,
                                         P, n_elem, na_shift, n_atoms, bin_stride);

    // finalize: decide output layout from out_size
    float* out = (float*)d_out;
    int mode;
    if (out_size == n_mol) mode = 0;
    else if (out_size == n_sp + n_mol) mode = 1;
    else if (out_size == n_sp) mode = 2;
    else mode = 0;

    int fin_n = (mode == 0) ? n_mol : ((n_sp > n_mol) ? n_sp : n_mol);
    int fin_grid = (fin_n + 255) / 256;
    finalize_kernel<<<fin_grid, 256>>>(energies, species, out, n_mol, n_sp, bin_stride, mode);
}

// round 2
// speedup vs baseline: 1.1082x; 1.1082x over previous
#include <cuda_runtime.h>

// ---------------------------------------------------------------------------
// EnergySRB: srb = pre[s0,s1] * exp(dfac[s0,s1]*d) * smooth_cutoff(d, rc)
//            out[mol] = energies[mol] + segment_sum(srb, mol = i0 / n_atoms)
//
// R2: packed 2-bit species table lives in SHARED memory (64KB/CTA) so the
// 32M random gathers ride the smem crossbar (~3 cyc/warp-op) instead of
// generating ~1 L1tex wavefront per lane. Scattered RED.F32 to 528B-strided
// global bins is now the expected bottleneck.
// ---------------------------------------------------------------------------

#define A2B_F 1.8897261258369282f
#define RC_F 9.826575854352027f          // 5.2 * A2B
#define INV_RC_F (1.0f / RC_F)

#define MAX_ATOKENS (512 * 1024)          // max total atoms for packed path
#define MAX_MOLS (8192)
#define BIN_STRIDE 132                    // 528B stride -> spreads L2 slice hash

__device__ unsigned int g_packed[MAX_ATOKENS / 16];   // 2-bit species codes
__device__ float g_bins[MAX_MOLS * BIN_STRIDE];       // padded molecule bins

// ---------------------------------------------------------------------------
// Init: pack species to 2 bits, zero the (strided) bins
// ---------------------------------------------------------------------------
__global__ void init_kernel(const int* __restrict__ species, int n_sp,
                            int n_mol, int bin_stride, int do_pack) {
    int t = blockIdx.x * blockDim.x + threadIdx.x;
    if (do_pack) {
        int nwords = (n_sp + 15) >> 4;
        if (t < nwords) {
            unsigned int w = 0;
            int base = t << 4;
            #pragma unroll
            for (int j = 0; j < 16; j++) {
                int a = base + j;
                unsigned int v = (a < n_sp) ? ((unsigned int)species[a] & 3u) : 0u;
                w |= v << (2 * j);
            }
            g_packed[t] = w;
        }
    }
    if (t < n_mol) g_bins[t * bin_stride] = 0.0f;
}

// ---------------------------------------------------------------------------
// Main pair kernel, smem-resident packed species table.
// smem layout: [0..31] u32 = 16 x float2 coef table, [32..32+nwords) packed.
// ---------------------------------------------------------------------------
__global__ void __launch_bounds__(512)
srb_kernel_smem(const int* __restrict__ idx0, const int* __restrict__ idx1,
                const float* __restrict__ dist,
                const float* __restrict__ pre_tab, const float* __restrict__ dfac_tab,
                int P, int n_elem, int na_shift, int bin_stride, int nwords)
{
    extern __shared__ unsigned int s_mem[];
    float2* s_tab = (float2*)s_mem;            // 16 float2 = 128B
    unsigned int* s_pk = s_mem + 32;           // packed species words

    int ne2 = n_elem * n_elem;
    for (int j = threadIdx.x; j < ne2; j += blockDim.x)
        s_tab[j] = make_float2(pre_tab[j], dfac_tab[j]);

    // cooperative load of packed table (vectorized)
    {
        const int4* __restrict__ src = (const int4*)g_packed;
        int4* dst = (int4*)s_pk;
        int nv4 = nwords >> 2;
        for (int j = threadIdx.x; j < nv4; j += blockDim.x)
            dst[j] = src[j];
        for (int j = (nv4 << 2) + threadIdx.x; j < nwords; j += blockDim.x)
            s_pk[j] = g_packed[j];
    }
    __syncthreads();

    int tid = blockIdx.x * blockDim.x + threadIdx.x;
    int stride = gridDim.x * blockDim.x;
    int nv = P >> 2;

    const int4* __restrict__ v0 = (const int4*)idx0;
    const int4* __restrict__ v1 = (const int4*)idx1;
    const float4* __restrict__ vd = (const float4*)dist;

    for (int i = tid; i < nv; i += stride) {
        int4 a = __ldcs(v0 + i);
        int4 b = __ldcs(v1 + i);
        float4 dd = __ldcs(vd + i);

        int ia[4] = {a.x, a.y, a.z, a.w};
        int ib[4] = {b.x, b.y, b.z, b.w};
        float dv[4] = {dd.x, dd.y, dd.z, dd.w};

        #pragma unroll
        for (int j = 0; j < 4; j++) {
            float d = dv[j] * A2B_F;
            float x = d * INV_RC_F;
            float u = fmaf(-x, x, 1.0f);           // 1 - (d/rc)^2
            if (u > 0.0f) {                        // cull first: saves LDS + atomic
                int i0 = ia[j], i1 = ib[j];
                unsigned int w0 = s_pk[i0 >> 4];
                unsigned int w1 = s_pk[i1 >> 4];
                int s0 = (int)((w0 >> ((i0 & 15) << 1)) & 3u);
                int s1 = (int)((w1 >> ((i1 & 15) << 1)) & 3u);
                float2 c = s_tab[(s0 << 2) + s1];  // n_elem==4 on packed path
                // exp(dfac*d) * exp(1 - 1/u) = exp(dfac*d + 1 - 1/u)
                float e = fmaf(c.y, d, 1.0f - __frcp_rn(u));
                float srb = c.x * __expf(e);
                int mol = i0 >> na_shift;
                atomicAdd(&g_bins[mol * bin_stride], srb);
            }
        }
    }

    // tail (P % 4)
    int rem = P & 3;
    if (tid < rem) {
        int p = (nv << 2) + tid;
        int i0 = idx0[p], i1 = idx1[p];
        float d = dist[p] * A2B_F;
        float x = d * INV_RC_F;
        float u = fmaf(-x, x, 1.0f);
        if (u > 0.0f) {
            unsigned int w0 = s_pk[i0 >> 4];
            unsigned int w1 = s_pk[i1 >> 4];
            int s0 = (int)((w0 >> ((i0 & 15) << 1)) & 3u);
            int s1 = (int)((w1 >> ((i1 & 15) << 1)) & 3u);
            float2 c = s_tab[(s0 << 2) + s1];
            float e = fmaf(c.y, d, 1.0f - __frcp_rn(u));
            float srb = c.x * __expf(e);
            int mol = i0 >> na_shift;
            atomicAdd(&g_bins[mol * bin_stride], srb);
        }
    }
}

// ---------------------------------------------------------------------------
// Generic fallback (species gathered straight from global, any n_elem/shape)
// ---------------------------------------------------------------------------
__global__ void __launch_bounds__(256)
srb_kernel_generic(const int* __restrict__ idx0, const int* __restrict__ idx1,
                   const float* __restrict__ dist, const int* __restrict__ species,
                   const float* __restrict__ pre_tab, const float* __restrict__ dfac_tab,
                   int P, int n_elem, int na_shift, int n_atoms, int bin_stride)
{
    __shared__ float2 s_tab[64];
    int ne2 = n_elem * n_elem;
    for (int j = threadIdx.x; j < ne2; j += blockDim.x)
        s_tab[j] = make_float2(pre_tab[j], dfac_tab[j]);
    __syncthreads();

    int tid = blockIdx.x * blockDim.x + threadIdx.x;
    int stride = gridDim.x * blockDim.x;
    for (int p = tid; p < P; p += stride) {
        int i0 = idx0[p], i1 = idx1[p];
        float d = dist[p] * A2B_F;
        float x = d * INV_RC_F;
        float u = fmaf(-x, x, 1.0f);
        if (u > 0.0f) {
            int s0 = species[i0];
            int s1 = species[i1];
            float2 c = s_tab[s0 * n_elem + s1];
            float e = fmaf(c.y, d, 1.0f - __frcp_rn(u));
            float srb = c.x * __expf(e);
            int mol = (na_shift >= 0) ? (i0 >> na_shift) : (i0 / n_atoms);
            atomicAdd(&g_bins[mol * bin_stride], srb);
        }
    }
}

// ---------------------------------------------------------------------------
// Finalize: out = [species (as float), energies + bins]  or just the energies
// ---------------------------------------------------------------------------
__global__ void finalize_kernel(const float* __restrict__ energies,
                                const int* __restrict__ species,
                                float* __restrict__ out,
                                int n_mol, int n_sp, int bin_stride, int mode) {
    int t = blockIdx.x * blockDim.x + threadIdx.x;
    if (mode == 1) {
        if (t < n_sp) out[t] = (float)species[t];
        if (t < n_mol) out[n_sp + t] = energies[t] + g_bins[t * bin_stride];
    } else if (mode == 2) {
        if (t < n_sp) out[t] = (float)species[t];
    } else {
        if (t < n_mol) out[t] = energies[t] + g_bins[t * bin_stride];
    }
}

// ---------------------------------------------------------------------------
extern "C" void kernel_launch(void* const* d_in, const int* in_sizes, int n_in,
                              void* d_out, int out_size) {
    const int*   species  = (const int*)d_in[0];
    const float* energies = (const float*)d_in[1];
    const int*   ai12     = (const int*)d_in[2];
    const float* dist     = (const float*)d_in[3];
    const float* pre_tab  = (const float*)d_in[4];
    const float* dfac_tab = (const float*)d_in[5];

    int n_sp  = in_sizes[0];
    int n_mol = in_sizes[1];
    int P     = in_sizes[3];
    int n_atoms = (n_mol > 0) ? (n_sp / n_mol) : 1;
    if (n_atoms < 1) n_atoms = 1;

    int n_elem = 1;
    while (n_elem * n_elem < in_sizes[4]) n_elem++;

    int na_shift = -1;
    if ((n_atoms & (n_atoms - 1)) == 0) {
        int s = 0; int v = n_atoms;
        while (v > 1) { v >>= 1; s++; }
        na_shift = s;
    }

    bool packed = (n_elem == 4) && (n_sp <= MAX_ATOKENS) && (na_shift >= 0);
    int bin_stride = (n_mol <= MAX_MOLS) ? BIN_STRIDE : 1;

    int nwords = (n_sp + 15) >> 4;
    // pad nwords to multiple of 4 for int4 smem copy
    int nwords_pad = (nwords + 3) & ~3;

    // init: pack + zero bins
    int init_n = n_mol;
    if (packed && nwords > init_n) init_n = nwords;
    int init_grid = (init_n + 255) / 256;
    init_kernel<<<init_grid, 256>>>(species, n_sp, n_mol, bin_stride, packed ? 1 : 0);

    const int* idx0 = ai12;
    const int* idx1 = ai12 + P;

    if (packed) {
        size_t smem_bytes = (size_t)(32 + nwords_pad) * sizeof(unsigned int);
        cudaFuncSetAttribute(srb_kernel_smem,
                             cudaFuncAttributeMaxDynamicSharedMemorySize,
                             (int)smem_bytes);
        // 3 CTAs/SM at 64KB smem -> 444 CTAs persistent
        int grid = 148 * 3;
        long long want = ((long long)(P >> 2) + 511) / 512;
        if (want < grid) grid = (int)(want > 0 ? want : 1);
        srb_kernel_smem<<<grid, 512, smem_bytes>>>(idx0, idx1, dist,
                                                   pre_tab, dfac_tab,
                                                   P, n_elem, na_shift,
                                                   bin_stride, nwords_pad);
    } else {
        long long want = ((long long)P + 255) / 256;
        int grid = (want > 4736) ? 4736 : (int)(want > 0 ? want : 1);
        srb_kernel_generic<<<grid, 256>>>(idx0, idx1, dist, species,
                                          pre_tab, dfac_tab,
                                          P, n_elem, na_shift, n_atoms, bin_stride);
    }

    // finalize: decide output layout from out_size
    float* out = (float*)d_out;
    int mode;
    if (out_size == n_mol) mode = 0;
    else if (out_size == n_sp + n_mol) mode = 1;
    else if (out_size == n_sp) mode = 2;
    else mode = 0;

    int fin_n = (mode == 0) ? n_mol : ((n_sp > n_mol) ? n_sp : n_mol);
    int fin_grid = (fin_n + 255) / 256;
    finalize_kernel<<<fin_grid, 256>>>(energies, species, out, n_mol, n_sp, bin_stride, mode);
}